// round 4
// baseline (speedup 1.0000x reference)
#include <cuda_runtime.h>
#include <math.h>

#define B_    8
#define C_    63
#define S_    2048
#define F_    5
#define E_    315
#define L1_   1023
#define L2_   511
#define L3_   255
#define O_    32
#define H_    64
#define EPG_  504
#define G_    (B_*L1_)
#define NE_   ((long)G_*EPG_)
#define NEG_INF (-3.402823466e38f)

constexpr long SZ_X1     = (long)B_*L1_*E_;
constexpr long SZ_X2     = (long)B_*L2_*E_;
constexpr long SZ_X3     = (long)B_*L3_*E_;
constexpr long SZ_POS2   = (long)L2_*C_;
constexpr long SZ_POS3   = (long)L3_*C_;
constexpr long SZ_Q1     = (long)B_*L2_*E_;
constexpr long SZ_KV1    = (long)B_*L3_*2*E_;
constexpr long SZ_P1     = (long)B_*3*L2_*L3_;
constexpr long SZ_O1     = SZ_Q1;
constexpr long SZ_X2A    = SZ_Q1;
constexpr long SZ_Q2     = (long)B_*L1_*E_;
constexpr long SZ_KV2    = (long)B_*L2_*2*E_;
constexpr long SZ_P2     = (long)B_*3*L1_*L2_;
constexpr long SZ_O2     = SZ_Q2;
constexpr long SZ_X1A    = SZ_Q2;
constexpr long SZ_XGRAPH = (long)G_*O_;
constexpr long SZ_XGATES = (long)G_*3*H_;
constexpr long SZ_GRUOUT = (long)G_*H_;
constexpr long SZ_SCORES = (long)G_*3;

constexpr long OFF_X1     = 0;
constexpr long OFF_X2     = OFF_X1     + SZ_X1;
constexpr long OFF_X3     = OFF_X2     + SZ_X2;
constexpr long OFF_POS2   = OFF_X3     + SZ_X3;
constexpr long OFF_POS3   = OFF_POS2   + SZ_POS2;
constexpr long OFF_Q1     = OFF_POS3   + SZ_POS3;
constexpr long OFF_KV1    = OFF_Q1     + SZ_Q1;
constexpr long OFF_P1     = OFF_KV1    + SZ_KV1;
constexpr long OFF_O1     = OFF_P1     + SZ_P1;
constexpr long OFF_X2A    = OFF_O1     + SZ_O1;
constexpr long OFF_Q2     = OFF_X2A    + SZ_X2A;
constexpr long OFF_KV2    = OFF_Q2     + SZ_Q2;
constexpr long OFF_P2     = OFF_KV2    + SZ_KV2;
constexpr long OFF_O2     = OFF_P2     + SZ_P2;
constexpr long OFF_X1A    = OFF_O2     + SZ_O2;
constexpr long OFF_XGRAPH = OFF_X1A    + SZ_X1A;
constexpr long OFF_XGATES = OFF_XGRAPH + SZ_XGRAPH;
constexpr long OFF_GRUOUT = OFF_XGATES + SZ_XGATES;
constexpr long OFF_SCORES = OFF_GRUOUT + SZ_GRUOUT;
constexpr long SCRATCH_TOTAL = OFF_SCORES + SZ_SCORES;

__device__ float g_scratch[SCRATCH_TOTAL];

// -------- adaptive avg pool over first dim of [L, 63] (fp64 acc) --------
__global__ void pool_k(const float* __restrict__ in, float* __restrict__ out,
                       int Lin, int Lout) {
    int idx = blockIdx.x * blockDim.x + threadIdx.x;
    if (idx >= Lout * C_) return;
    int i = idx / C_, c = idx - C_ * i;
    int s = (i * Lin) / Lout;
    int e = ((i + 1) * Lin + Lout - 1) / Lout;
    double acc = 0.0;
    for (int l = s; l < e; l++) acc += (double)in[l * C_ + c];
    out[idx] = (float)(acc / (double)(e - s));
}

// -------- conv (1x3, stride2, 63->63 channel mix), fp64 accumulation --------
__global__ __launch_bounds__(256) void conv_k(
    const float* __restrict__ in, const float* __restrict__ W,
    const float* __restrict__ bias, float* __restrict__ out,
    int Lin, int Lout, int inOrig) {
    int l0 = blockIdx.x * 64;
    int bf = blockIdx.y;
    int b = bf / F_, f = bf - b * F_;
    __shared__ double As[16][65];
    __shared__ double Bs[16][65];
    int tid = threadIdx.x;
    int tx = tid & 15, ty = tid >> 4;
    double acc[4][4];
#pragma unroll
    for (int i = 0; i < 4; i++)
#pragma unroll
        for (int j = 0; j < 4; j++) acc[i][j] = 0.0;

    for (int k0 = 0; k0 < 189; k0 += 16) {
        for (int t = tid; t < 1024; t += 256) {
            int co = t >> 4, kk = t & 15;
            int kidx = k0 + kk;
            As[kk][co] = (co < 63 && kidx < 189) ? (double)W[co * 189 + kidx] : 0.0;
        }
        for (int t = tid; t < 1024; t += 256) {
            int l = t & 63, kk = t >> 6;
            int kidx = k0 + kk;
            double v = 0.0;
            int gl = l0 + l;
            if (kidx < 189 && gl < Lout) {
                int ci = kidx / 3, kx = kidx - ci * 3;
                int si = 2 * gl + kx;
                if (inOrig)
                    v = (double)in[((long)(b * 63 + ci) * Lin + si) * 5 + f];
                else
                    v = (double)in[((long)b * Lin + si) * 315 + f * 63 + ci];
            }
            Bs[kk][l] = v;
        }
        __syncthreads();
#pragma unroll
        for (int kk = 0; kk < 16; kk++) {
            double av[4], bv[4];
#pragma unroll
            for (int i = 0; i < 4; i++) { av[i] = As[kk][ty * 4 + i]; bv[i] = Bs[kk][tx * 4 + i]; }
#pragma unroll
            for (int i = 0; i < 4; i++)
#pragma unroll
                for (int j = 0; j < 4; j++) acc[i][j] = fma(av[i], bv[j], acc[i][j]);
        }
        __syncthreads();
    }
#pragma unroll
    for (int i = 0; i < 4; i++) {
        int co = ty * 4 + i;
        if (co >= 63) continue;
#pragma unroll
        for (int j = 0; j < 4; j++) {
            int l = l0 + tx * 4 + j;
            if (l >= Lout) continue;
            out[((long)b * Lout + l) * 315 + f * 63 + co] = (float)(acc[i][j] + (double)bias[co]);
        }
    }
}

// add pos (layout [L,63]) to flat tensor [B,L,315]
__global__ void addpos_k(float* __restrict__ xf, const float* __restrict__ pos, int L) {
    long idx = (long)blockIdx.x * 256 + threadIdx.x;
    long tot = (long)B_ * L * 315;
    if (idx >= tot) return;
    int rem = (int)(idx % 315);
    long bl = idx / 315;
    int l = (int)(bl % L);
    xf[idx] += pos[l * 63 + (rem % 63)];
}

// -------- generic GEMM, fp32 in/out, fp64 accumulation --------
__global__ __launch_bounds__(256) void gemm_k(
    const float* __restrict__ A, int lda, long sAo, long sAi,
    const float* __restrict__ Bm, int ldb, long sBo, long sBi,
    float* __restrict__ Cm, int ldc, long sCo, long sCi,
    const float* __restrict__ bias,
    int M, int N, int K, double alpha, int transB, int nInner) {
    int z = blockIdx.z;
    int zo = z / nInner, zi = z - zo * nInner;
    A += zo * sAo + zi * sAi;
    Bm += zo * sBo + zi * sBi;
    Cm += zo * sCo + zi * sCi;
    __shared__ double As[16][65];
    __shared__ double Bs[16][65];
    int m0 = blockIdx.y * 64, n0 = blockIdx.x * 64;
    int tid = threadIdx.x;
    int tx = tid & 15, ty = tid >> 4;
    double acc[4][4];
#pragma unroll
    for (int i = 0; i < 4; i++)
#pragma unroll
        for (int j = 0; j < 4; j++) acc[i][j] = 0.0;

    for (int k0 = 0; k0 < K; k0 += 16) {
        for (int t = tid; t < 1024; t += 256) {
            int m = t >> 4, kk = t & 15;
            int gm = m0 + m, gk = k0 + kk;
            As[kk][m] = (gm < M && gk < K) ? (double)A[(long)gm * lda + gk] : 0.0;
        }
        if (transB) {
            for (int t = tid; t < 1024; t += 256) {
                int n = t >> 4, kk = t & 15;
                int gn = n0 + n, gk = k0 + kk;
                Bs[kk][n] = (gn < N && gk < K) ? (double)Bm[(long)gn * ldb + gk] : 0.0;
            }
        } else {
            for (int t = tid; t < 1024; t += 256) {
                int n = t & 63, kk = t >> 6;
                int gn = n0 + n, gk = k0 + kk;
                Bs[kk][n] = (gn < N && gk < K) ? (double)Bm[(long)gk * ldb + gn] : 0.0;
            }
        }
        __syncthreads();
#pragma unroll
        for (int kk = 0; kk < 16; kk++) {
            double av[4], bv[4];
#pragma unroll
            for (int i = 0; i < 4; i++) { av[i] = As[kk][ty * 4 + i]; bv[i] = Bs[kk][tx * 4 + i]; }
#pragma unroll
            for (int i = 0; i < 4; i++)
#pragma unroll
                for (int j = 0; j < 4; j++) acc[i][j] = fma(av[i], bv[j], acc[i][j]);
        }
        __syncthreads();
    }
#pragma unroll
    for (int i = 0; i < 4; i++) {
        int gm = m0 + ty * 4 + i;
        if (gm >= M) continue;
#pragma unroll
        for (int j = 0; j < 4; j++) {
            int gn = n0 + tx * 4 + j;
            if (gn >= N) continue;
            double v = alpha * acc[i][j];
            if (bias) v += (double)bias[gn];
            Cm[(long)gm * ldc + gn] = (float)v;
        }
    }
}

// -------- row softmax, warp per row, Ld <= 512, fp64 exp/sum --------
__global__ void softmax_k(float* __restrict__ P, int rows, int Ld) {
    int warp = (blockIdx.x * blockDim.x + threadIdx.x) >> 5;
    int lane = threadIdx.x & 31;
    if (warp >= rows) return;
    float* p = P + (long)warp * Ld;
    float v[16];
    float m = NEG_INF;
#pragma unroll
    for (int q = 0; q < 16; q++) {
        int i = lane + (q << 5);
        v[q] = (i < Ld) ? p[i] : NEG_INF;
        m = fmaxf(m, v[q]);
    }
#pragma unroll
    for (int off = 16; off; off >>= 1) m = fmaxf(m, __shfl_xor_sync(0xffffffffu, m, off));
    double ex[16];
    double s = 0.0;
#pragma unroll
    for (int q = 0; q < 16; q++) {
        int i = lane + (q << 5);
        ex[q] = (i < Ld) ? exp((double)v[q] - (double)m) : 0.0;
        s += ex[q];
    }
#pragma unroll
    for (int off = 16; off; off >>= 1) s += __shfl_xor_sync(0xffffffffu, s, off);
    double inv = 1.0 / s;
#pragma unroll
    for (int q = 0; q < 16; q++) {
        int i = lane + (q << 5);
        if (i < Ld) p[i] = (float)(ex[q] * inv);
    }
}

// -------- GATv2 per graph + mean pool, fp64 reductions --------
__global__ __launch_bounds__(256) void gat_k(
    const float* __restrict__ xfeat, const int* __restrict__ edge_index,
    const float* __restrict__ edge_attr,
    const float* __restrict__ wl, const float* __restrict__ blv,
    const float* __restrict__ wr, const float* __restrict__ brv,
    const float* __restrict__ wev, const float* __restrict__ attv,
    const float* __restrict__ gbias, float* __restrict__ xgraph) {
    int g = blockIdx.x;
    int tid = threadIdx.x;
    __shared__ float xn[E_];
    __shared__ float xl[63 * 32], xr[63 * 32];
    __shared__ double outacc[63 * 32];
    __shared__ double la[63], ssumd[63];
    __shared__ float scf[EPG_ + 63], eav[EPG_];
    __shared__ int srcl[EPG_ + 63], dstl[EPG_ + 63], deg[63];
    __shared__ unsigned long long smaxll[63];
    __shared__ float wls[160], wrs[160], wes[32], atts[32];

    const long ebase = (long)g * EPG_;
    for (int i = tid; i < E_; i += 256) xn[i] = xfeat[(long)g * E_ + i];
    if (tid < 160) { wls[tid] = wl[tid]; wrs[tid] = wr[tid]; }
    if (tid < 32)  { wes[tid] = wev[tid]; atts[tid] = attv[tid]; }
    if (tid < 63)  { deg[tid] = 0; la[tid] = 0.0; ssumd[tid] = 0.0; smaxll[tid] = 0ull;
                     srcl[EPG_ + tid] = tid; dstl[EPG_ + tid] = tid; }
    for (int i = tid; i < 2016; i += 256) outacc[i] = 0.0;
    for (int e = tid; e < EPG_; e += 256) {
        srcl[e] = edge_index[ebase + e] - g * 63;
        dstl[e] = edge_index[NE_ + ebase + e] - g * 63;
        eav[e]  = edge_attr[ebase + e];
    }
    __syncthreads();
    for (int i = tid; i < 2016; i += 256) {
        int nd = i >> 5, k = i & 31;
        const float* xv = &xn[nd * 5];
        double sl = (double)blv[k], sr = (double)brv[k];
#pragma unroll
        for (int f = 0; f < 5; f++) {
            sl = fma((double)wls[k * 5 + f], (double)xv[f], sl);
            sr = fma((double)wrs[k * 5 + f], (double)xv[f], sr);
        }
        xl[i] = (float)sl; xr[i] = (float)sr;
    }
    for (int e = tid; e < EPG_; e += 256) {
        atomicAdd(&deg[dstl[e]], 1);
        atomicAdd(&la[dstl[e]], (double)eav[e]);
    }
    __syncthreads();
    if (tid < 63) la[tid] = la[tid] / fmax((double)deg[tid], 1.0);
    __syncthreads();
    for (int e = tid; e < EPG_ + 63; e += 256) {
        int sn = srcl[e], d = dstl[e];
        double ea = (e < EPG_) ? (double)eav[e] : la[d];
        double sco = 0.0;
#pragma unroll
        for (int k = 0; k < 32; k++) {
            double m = (double)xl[sn * 32 + k] + (double)xr[d * 32 + k] + (double)wes[k] * ea;
            m = (m > 0.0) ? m : 0.2 * m;
            sco = fma(m, (double)atts[k], sco);
        }
        float scof = (float)sco;
        scf[e] = scof;
        unsigned long long u = __double_as_longlong((double)scof) ;
        u = (u & 0x8000000000000000ull) ? ~u : (u | 0x8000000000000000ull);
        atomicMax(&smaxll[d], u);
    }
    __syncthreads();
    for (int e = tid; e < EPG_ + 63; e += 256) {
        int sn = srcl[e], d = dstl[e];
        unsigned long long u = smaxll[d];
        double mx = __longlong_as_double((u & 0x8000000000000000ull) ? (long long)(u & 0x7fffffffffffffffull) : (long long)~u);
        double exv = exp((double)scf[e] - mx);
        atomicAdd(&ssumd[d], exv);
#pragma unroll
        for (int k = 0; k < 32; k++) atomicAdd(&outacc[d * 32 + k], exv * (double)xl[sn * 32 + k]);
    }
    __syncthreads();
    if (tid < 32) {
        double s = 0.0;
        for (int d = 0; d < 63; d++) s += outacc[d * 32 + tid] / ssumd[d];
        xgraph[(long)g * 32 + tid] = (float)(s * (1.0 / 63.0) + (double)gbias[tid]);
    }
}

// -------- GRU scan: one block per batch row, fp64 recurrence --------
__global__ __launch_bounds__(192) void gru_k(
    const float* __restrict__ xgates, const float* __restrict__ whh,
    const float* __restrict__ bhh, float* __restrict__ gruout) {
    int b = blockIdx.x;
    int t = threadIdx.x;
    __shared__ double hs[64];
    __shared__ double hg[192];
    double w[64];
#pragma unroll
    for (int j = 0; j < 64; j++) w[j] = (double)whh[t * 64 + j];
    double bh = (double)bhh[t];
    if (t < 64) hs[t] = 0.0;
    __syncthreads();
    for (int l = 0; l < L1_; l++) {
        double s = bh;
#pragma unroll
        for (int j = 0; j < 64; j++) s = fma(w[j], hs[j], s);
        hg[t] = s;
        __syncthreads();
        if (t < 64) {
            const float* xg = xgates + ((long)b * L1_ + l) * 192;
            double r = 1.0 / (1.0 + exp(-((double)xg[t] + hg[t])));
            double z = 1.0 / (1.0 + exp(-((double)xg[64 + t] + hg[64 + t])));
            double n = tanh((double)xg[128 + t] + r * hg[128 + t]);
            double hnew = (1.0 - z) * n + z * hs[t];
            hs[t] = hnew;
            gruout[((long)b * L1_ + l) * 64 + t] = (float)hnew;
        }
        __syncthreads();
    }
}

// -------- classifier, fp64 acc --------
__global__ __launch_bounds__(256) void cls_k(
    const float* __restrict__ gru, const float* __restrict__ w1,
    const float* __restrict__ b1, const float* __restrict__ w2,
    const float* __restrict__ b2, float* __restrict__ sc) {
    __shared__ float s1[2048], s2[96], sb1[32], sb2[3];
    int t = threadIdx.x;
    for (int i = t; i < 2048; i += 256) s1[i] = w1[i];
    if (t < 96) s2[t] = w2[t];
    if (t < 32) sb1[t] = b1[t];
    if (t < 3)  sb2[t] = b2[t];
    __syncthreads();
    int g = blockIdx.x * 256 + t;
    if (g >= G_) return;
    float h[64];
    const float* gr = gru + (long)g * 64;
#pragma unroll
    for (int j = 0; j < 64; j++) h[j] = gr[j];
    double o0 = (double)sb2[0], o1 = (double)sb2[1], o2 = (double)sb2[2];
    for (int u = 0; u < 32; u++) {
        double a = (double)sb1[u];
#pragma unroll
        for (int j = 0; j < 64; j++) a = fma((double)s1[u * 64 + j], (double)h[j], a);
        a = fmax(a, 0.0);
        o0 = fma((double)s2[u], a, o0);
        o1 = fma((double)s2[32 + u], a, o1);
        o2 = fma((double)s2[64 + u], a, o2);
    }
    sc[(long)g * 3 + 0] = (float)o0;
    sc[(long)g * 3 + 1] = (float)o1;
    sc[(long)g * 3 + 2] = (float)o2;
}

// -------- top-5 per (b, class); out: 24 means then 120 idx-as-float --------
__global__ __launch_bounds__(128) void topk_k(const float* __restrict__ scores,
                                              float* __restrict__ out) {
    int bc = blockIdx.x;
    int b = bc / 3, c = bc - 3 * b;
    __shared__ float sv[L1_];
    __shared__ float bval[128];
    __shared__ int bidx[128];
    __shared__ float ssum;
    int t = threadIdx.x;
    for (int i = t; i < L1_; i += 128) sv[i] = scores[((long)b * L1_ + i) * 3 + c];
    if (t == 0) ssum = 0.f;
    __syncthreads();
    for (int k = 0; k < 5; k++) {
        float mv = NEG_INF; int mi = 0x7fffffff;
        for (int i = t; i < L1_; i += 128) {
            float v = sv[i];
            if (v > mv) { mv = v; mi = i; }
        }
        bval[t] = mv; bidx[t] = mi;
        __syncthreads();
        for (int off = 64; off; off >>= 1) {
            if (t < off) {
                if (bval[t + off] > bval[t] ||
                    (bval[t + off] == bval[t] && bidx[t + off] < bidx[t])) {
                    bval[t] = bval[t + off]; bidx[t] = bidx[t + off];
                }
            }
            __syncthreads();
        }
        if (t == 0) {
            out[24 + (b * 5 + k) * 3 + c] = (float)bidx[0];
            ssum += bval[0];
            sv[bidx[0]] = NEG_INF;
        }
        __syncthreads();
    }
    if (t == 0) out[b * 3 + c] = ssum * 0.2f;
}

extern "C" void kernel_launch(void* const* d_in, const int* in_sizes, int n_in,
                              void* d_out, int out_size) {
    const float* x        = (const float*)d_in[0];
    const float* c1w      = (const float*)d_in[1];
    const float* c1b      = (const float*)d_in[2];
    const float* c2w      = (const float*)d_in[3];
    const float* c2b      = (const float*)d_in[4];
    const float* c3w      = (const float*)d_in[5];
    const float* c3b      = (const float*)d_in[6];
    const float* pos_emb  = (const float*)d_in[7];
    const float* ain_w    = (const float*)d_in[8];
    const float* ain_b    = (const float*)d_in[9];
    const float* aout_w   = (const float*)d_in[10];
    const float* aout_b   = (const float*)d_in[11];
    const float* gat_wl   = (const float*)d_in[12];
    const float* gat_bl   = (const float*)d_in[13];
    const float* gat_wr   = (const float*)d_in[14];
    const float* gat_br   = (const float*)d_in[15];
    const float* gat_we   = (const float*)d_in[16];
    const float* gat_att  = (const float*)d_in[17];
    const float* gat_bias = (const float*)d_in[18];
    const float* gru_wih  = (const float*)d_in[19];
    const float* gru_whh  = (const float*)d_in[20];
    const float* gru_bih  = (const float*)d_in[21];
    const float* gru_bhh  = (const float*)d_in[22];
    const float* fc1_w    = (const float*)d_in[23];
    const float* fc1_b    = (const float*)d_in[24];
    const float* fc2_w    = (const float*)d_in[25];
    const float* fc2_b    = (const float*)d_in[26];
    const float* e_attr   = (const float*)d_in[27];
    const int*   e_index  = (const int*)d_in[28];
    float* out = (float*)d_out;

    float* s;
    cudaGetSymbolAddress((void**)&s, g_scratch);
    const double iscale = 0.09759000729485331905;  // 1/sqrt(105)

    // convs (pre-pos chaining)
    conv_k<<<dim3(16, 40), 256>>>(x, c1w, c1b, s + OFF_X1, S_, L1_, 1);
    conv_k<<<dim3(8, 40), 256>>>(s + OFF_X1, c2w, c2b, s + OFF_X2, L1_, L2_, 0);
    conv_k<<<dim3(4, 40), 256>>>(s + OFF_X2, c3w, c3b, s + OFF_X3, L2_, L3_, 0);
    // pos embeddings
    pool_k<<<(L2_ * C_ + 255) / 256, 256>>>(pos_emb, s + OFF_POS2, L1_, L2_);
    pool_k<<<(L3_ * C_ + 255) / 256, 256>>>(s + OFF_POS2, s + OFF_POS3, L2_, L3_);
    addpos_k<<<(int)((SZ_X1 + 255) / 256), 256>>>(s + OFF_X1, pos_emb, L1_);
    addpos_k<<<(int)((SZ_X2 + 255) / 256), 256>>>(s + OFF_X2, s + OFF_POS2, L2_);
    addpos_k<<<(int)((SZ_X3 + 255) / 256), 256>>>(s + OFF_X3, s + OFF_POS3, L3_);

    // ---- MHA1: q = x2 [B,511,315], kv = x3 [B,255,315] ----
    int M1 = B_ * L2_, M3 = B_ * L3_;
    gemm_k<<<dim3(5, (M1 + 63) / 64, 1), 256>>>(s + OFF_X2, 315, 0, 0, ain_w, 315, 0, 0,
        s + OFF_Q1, 315, 0, 0, ain_b, M1, 315, 315, 1.0, 1, 1);
    gemm_k<<<dim3(5, (M3 + 63) / 64, 1), 256>>>(s + OFF_X3, 315, 0, 0, ain_w + 315 * 315, 315, 0, 0,
        s + OFF_KV1, 315, 0, 0, ain_b + 315, M3, 315, 315, 1.0, 1, 1);
    gemm_k<<<dim3(5, (M3 + 63) / 64, 1), 256>>>(s + OFF_X3, 315, 0, 0, ain_w + 630 * 315, 315, 0, 0,
        s + OFF_KV1 + (long)M3 * 315, 315, 0, 0, ain_b + 630, M3, 315, 315, 1.0, 1, 1);
    gemm_k<<<dim3(4, 8, 24), 256>>>(
        s + OFF_Q1, 315, (long)L2_ * 315, 105,
        s + OFF_KV1, 315, (long)L3_ * 315, 105,
        s + OFF_P1, 255, (long)3 * L2_ * L3_, (long)L2_ * L3_,
        nullptr, L2_, L3_, 105, iscale, 1, 3);
    softmax_k<<<(B_ * 3 * L2_ + 7) / 8, 256>>>(s + OFF_P1, B_ * 3 * L2_, L3_);
    gemm_k<<<dim3(2, 8, 24), 256>>>(
        s + OFF_P1, 255, (long)3 * L2_ * L3_, (long)L2_ * L3_,
        s + OFF_KV1 + (long)M3 * 315, 315, (long)L3_ * 315, 105,
        s + OFF_O1, 315, (long)L2_ * 315, 105,
        nullptr, L2_, 105, L3_, 1.0, 0, 3);
    gemm_k<<<dim3(5, (M1 + 63) / 64, 1), 256>>>(s + OFF_O1, 315, 0, 0, aout_w, 315, 0, 0,
        s + OFF_X2A, 315, 0, 0, aout_b, M1, 315, 315, 1.0, 1, 1);

    // ---- MHA2: q = x1 [B,1023,315], kv = x2a [B,511,315] ----
    int M0 = B_ * L1_;
    gemm_k<<<dim3(5, (M0 + 63) / 64, 1), 256>>>(s + OFF_X1, 315, 0, 0, ain_w, 315, 0, 0,
        s + OFF_Q2, 315, 0, 0, ain_b, M0, 315, 315, 1.0, 1, 1);
    gemm_k<<<dim3(5, (M1 + 63) / 64, 1), 256>>>(s + OFF_X2A, 315, 0, 0, ain_w + 315 * 315, 315, 0, 0,
        s + OFF_KV2, 315, 0, 0, ain_b + 315, M1, 315, 315, 1.0, 1, 1);
    gemm_k<<<dim3(5, (M1 + 63) / 64, 1), 256>>>(s + OFF_X2A, 315, 0, 0, ain_w + 630 * 315, 315, 0, 0,
        s + OFF_KV2 + (long)M1 * 315, 315, 0, 0, ain_b + 630, M1, 315, 315, 1.0, 1, 1);
    gemm_k<<<dim3(8, 16, 24), 256>>>(
        s + OFF_Q2, 315, (long)L1_ * 315, 105,
        s + OFF_KV2, 315, (long)L2_ * 315, 105,
        s + OFF_P2, 511, (long)3 * L1_ * L2_, (long)L1_ * L2_,
        nullptr, L1_, L2_, 105, iscale, 1, 3);
    softmax_k<<<(B_ * 3 * L1_ + 7) / 8, 256>>>(s + OFF_P2, B_ * 3 * L1_, L2_);
    gemm_k<<<dim3(2, 16, 24), 256>>>(
        s + OFF_P2, 511, (long)3 * L1_ * L2_, (long)L1_ * L2_,
        s + OFF_KV2 + (long)M1 * 315, 315, (long)L2_ * 315, 105,
        s + OFF_O2, 315, (long)L1_ * 315, 105,
        nullptr, L1_, 105, L2_, 1.0, 0, 3);
    gemm_k<<<dim3(5, (M0 + 63) / 64, 1), 256>>>(s + OFF_O2, 315, 0, 0, aout_w, 315, 0, 0,
        s + OFF_X1A, 315, 0, 0, aout_b, M0, 315, 315, 1.0, 1, 1);

    // ---- GAT per graph ----
    gat_k<<<G_, 256>>>(s + OFF_X1A, e_index, e_attr,
                       gat_wl, gat_bl, gat_wr, gat_br, gat_we, gat_att, gat_bias,
                       s + OFF_XGRAPH);

    // ---- GRU input gates + scan ----
    gemm_k<<<dim3(3, (G_ + 63) / 64, 1), 256>>>(s + OFF_XGRAPH, 32, 0, 0, gru_wih, 32, 0, 0,
        s + OFF_XGATES, 192, 0, 0, gru_bih, G_, 192, 32, 1.0, 1, 1);
    gru_k<<<B_, 192>>>(s + OFF_XGATES, gru_whh, gru_bhh, s + OFF_GRUOUT);

    // ---- classifier + top-k ----
    cls_k<<<(G_ + 255) / 256, 256>>>(s + OFF_GRUOUT, fc1_w, fc1_b, fc2_w, fc2_b,
                                     s + OFF_SCORES);
    topk_k<<<24, 128>>>(s + OFF_SCORES, out);
}

// round 5
// speedup vs baseline: 1.3014x; 1.3014x over previous
#include <cuda_runtime.h>
#include <math.h>

#define B_    8
#define C_    63
#define S_    2048
#define F_    5
#define E_    315
#define L1_   1023
#define L2_   511
#define L3_   255
#define O_    32
#define H_    64
#define EPG_  504
#define G_    (B_*L1_)
#define NE_   ((long)G_*EPG_)
#define NEG_INF (-3.402823466e38f)

constexpr long SZ_X1     = (long)B_*L1_*E_;
constexpr long SZ_X2     = (long)B_*L2_*E_;
constexpr long SZ_X3     = (long)B_*L3_*E_;
constexpr long SZ_POS2   = (long)L2_*C_;
constexpr long SZ_POS3   = (long)L3_*C_;
constexpr long SZ_Q1     = (long)B_*L2_*E_;
constexpr long SZ_KV1    = (long)B_*L3_*2*E_;
constexpr long SZ_P1     = (long)B_*3*L2_*L3_;
constexpr long SZ_O1     = SZ_Q1;
constexpr long SZ_X2A    = SZ_Q1;
constexpr long SZ_Q2     = (long)B_*L1_*E_;
constexpr long SZ_KV2    = (long)B_*L2_*2*E_;
constexpr long SZ_P2     = (long)B_*3*L1_*L2_;
constexpr long SZ_O2     = SZ_Q2;
constexpr long SZ_X1A    = SZ_Q2;
constexpr long SZ_XGRAPH = (long)G_*O_;
constexpr long SZ_XGATES = (long)G_*3*H_;
constexpr long SZ_GRUOUT = (long)G_*H_;
constexpr long SZ_SCORES = (long)G_*3;

constexpr long OFF_X1     = 0;
constexpr long OFF_X2     = OFF_X1     + SZ_X1;
constexpr long OFF_X3     = OFF_X2     + SZ_X2;
constexpr long OFF_POS2   = OFF_X3     + SZ_X3;
constexpr long OFF_POS3   = OFF_POS2   + SZ_POS2;
constexpr long OFF_Q1     = OFF_POS3   + SZ_POS3;
constexpr long OFF_KV1    = OFF_Q1     + SZ_Q1;
constexpr long OFF_P1     = OFF_KV1    + SZ_KV1;
constexpr long OFF_O1     = OFF_P1     + SZ_P1;
constexpr long OFF_X2A    = OFF_O1     + SZ_O1;
constexpr long OFF_Q2     = OFF_X2A    + SZ_X2A;
constexpr long OFF_KV2    = OFF_Q2     + SZ_Q2;
constexpr long OFF_P2     = OFF_KV2    + SZ_KV2;
constexpr long OFF_O2     = OFF_P2     + SZ_P2;
constexpr long OFF_X1A    = OFF_O2     + SZ_O2;
constexpr long OFF_XGRAPH = OFF_X1A    + SZ_X1A;
constexpr long OFF_XGATES = OFF_XGRAPH + SZ_XGRAPH;
constexpr long OFF_GRUOUT = OFF_XGATES + SZ_XGATES;
constexpr long OFF_SCORES = OFF_GRUOUT + SZ_GRUOUT;
constexpr long SCRATCH_TOTAL = OFF_SCORES + SZ_SCORES;

__device__ float g_scratch[SCRATCH_TOTAL];

// double-single compensated MAC: (hi,lo) += a*b, exact product + Knuth TwoSum.
// All via _rn intrinsics so ptxas cannot re-fuse/reassociate.
__device__ __forceinline__ void dsmac(float a, float b, float& hi, float& lo) {
    float p  = __fmul_rn(a, b);
    float e  = __fmaf_rn(a, b, -p);          // exact product error
    float s  = __fadd_rn(hi, p);
    float bb = __fsub_rn(s, hi);
    float err = __fadd_rn(__fsub_rn(hi, __fsub_rn(s, bb)), __fsub_rn(p, bb));
    hi = s;
    lo = __fadd_rn(lo, __fadd_rn(err, e));
}

// -------- adaptive avg pool over first dim of [L, 63] (fp64 acc) --------
__global__ void pool_k(const float* __restrict__ in, float* __restrict__ out,
                       int Lin, int Lout) {
    int idx = blockIdx.x * blockDim.x + threadIdx.x;
    if (idx >= Lout * C_) return;
    int i = idx / C_, c = idx - C_ * i;
    int s = (i * Lin) / Lout;
    int e = ((i + 1) * Lin + Lout - 1) / Lout;
    double acc = 0.0;
    for (int l = s; l < e; l++) acc += (double)in[l * C_ + c];
    out[idx] = (float)(acc / (double)(e - s));
}

// -------- conv (1x3, stride2, 63->63 channel mix), df64 accumulation --------
__global__ __launch_bounds__(256) void conv_k(
    const float* __restrict__ in, const float* __restrict__ W,
    const float* __restrict__ bias, float* __restrict__ out,
    int Lin, int Lout, int inOrig) {
    int l0 = blockIdx.x * 64;
    int bf = blockIdx.y;
    int b = bf / F_, f = bf - b * F_;
    __shared__ __align__(16) float As[16][68];
    __shared__ __align__(16) float Bs[16][68];
    int tid = threadIdx.x;
    int tx = tid & 15, ty = tid >> 4;
    float hi[4][4], lo[4][4];
#pragma unroll
    for (int i = 0; i < 4; i++)
#pragma unroll
        for (int j = 0; j < 4; j++) { hi[i][j] = 0.f; lo[i][j] = 0.f; }

    for (int k0 = 0; k0 < 189; k0 += 16) {
        for (int t = tid; t < 1024; t += 256) {
            int co = t >> 4, kk = t & 15;
            int kidx = k0 + kk;
            As[kk][co] = (co < 63 && kidx < 189) ? W[co * 189 + kidx] : 0.f;
        }
        for (int t = tid; t < 1024; t += 256) {
            int l = t & 63, kk = t >> 6;
            int kidx = k0 + kk;
            float v = 0.f;
            int gl = l0 + l;
            if (kidx < 189 && gl < Lout) {
                int ci = kidx / 3, kx = kidx - ci * 3;
                int si = 2 * gl + kx;
                if (inOrig)
                    v = in[((long)(b * 63 + ci) * Lin + si) * 5 + f];
                else
                    v = in[((long)b * Lin + si) * 315 + f * 63 + ci];
            }
            Bs[kk][l] = v;
        }
        __syncthreads();
#pragma unroll
        for (int kk = 0; kk < 16; kk++) {
            float4 a4 = *(const float4*)&As[kk][ty * 4];
            float4 b4 = *(const float4*)&Bs[kk][tx * 4];
            float av[4] = {a4.x, a4.y, a4.z, a4.w};
            float bv[4] = {b4.x, b4.y, b4.z, b4.w};
#pragma unroll
            for (int i = 0; i < 4; i++)
#pragma unroll
                for (int j = 0; j < 4; j++) dsmac(av[i], bv[j], hi[i][j], lo[i][j]);
        }
        __syncthreads();
    }
#pragma unroll
    for (int i = 0; i < 4; i++) {
        int co = ty * 4 + i;
        if (co >= 63) continue;
#pragma unroll
        for (int j = 0; j < 4; j++) {
            int l = l0 + tx * 4 + j;
            if (l >= Lout) continue;
            double v = (double)hi[i][j] + (double)lo[i][j] + (double)bias[co];
            out[((long)b * Lout + l) * 315 + f * 63 + co] = (float)v;
        }
    }
}

// add pos (layout [L,63]) to flat tensor [B,L,315]
__global__ void addpos_k(float* __restrict__ xf, const float* __restrict__ pos, int L) {
    long idx = (long)blockIdx.x * 256 + threadIdx.x;
    long tot = (long)B_ * L * 315;
    if (idx >= tot) return;
    int rem = (int)(idx % 315);
    long bl = idx / 315;
    int l = (int)(bl % L);
    xf[idx] += pos[l * 63 + (rem % 63)];
}

// -------- generic GEMM, fp32 in/out, df64 accumulation --------
__global__ __launch_bounds__(256) void gemm_k(
    const float* __restrict__ A, int lda, long sAo, long sAi,
    const float* __restrict__ Bm, int ldb, long sBo, long sBi,
    float* __restrict__ Cm, int ldc, long sCo, long sCi,
    const float* __restrict__ bias,
    int M, int N, int K, double alpha, int transB, int nInner) {
    int z = blockIdx.z;
    int zo = z / nInner, zi = z - zo * nInner;
    A += zo * sAo + zi * sAi;
    Bm += zo * sBo + zi * sBi;
    Cm += zo * sCo + zi * sCi;
    __shared__ __align__(16) float As[16][68];
    __shared__ __align__(16) float Bs[16][68];
    int m0 = blockIdx.y * 64, n0 = blockIdx.x * 64;
    int tid = threadIdx.x;
    int tx = tid & 15, ty = tid >> 4;
    float hi[4][4], lo[4][4];
#pragma unroll
    for (int i = 0; i < 4; i++)
#pragma unroll
        for (int j = 0; j < 4; j++) { hi[i][j] = 0.f; lo[i][j] = 0.f; }

    for (int k0 = 0; k0 < K; k0 += 16) {
        for (int t = tid; t < 1024; t += 256) {
            int m = t >> 4, kk = t & 15;
            int gm = m0 + m, gk = k0 + kk;
            As[kk][m] = (gm < M && gk < K) ? A[(long)gm * lda + gk] : 0.f;
        }
        if (transB) {
            for (int t = tid; t < 1024; t += 256) {
                int n = t >> 4, kk = t & 15;
                int gn = n0 + n, gk = k0 + kk;
                Bs[kk][n] = (gn < N && gk < K) ? Bm[(long)gn * ldb + gk] : 0.f;
            }
        } else {
            for (int t = tid; t < 1024; t += 256) {
                int n = t & 63, kk = t >> 6;
                int gn = n0 + n, gk = k0 + kk;
                Bs[kk][n] = (gn < N && gk < K) ? Bm[(long)gk * ldb + gn] : 0.f;
            }
        }
        __syncthreads();
#pragma unroll
        for (int kk = 0; kk < 16; kk++) {
            float4 a4 = *(const float4*)&As[kk][ty * 4];
            float4 b4 = *(const float4*)&Bs[kk][tx * 4];
            float av[4] = {a4.x, a4.y, a4.z, a4.w};
            float bv[4] = {b4.x, b4.y, b4.z, b4.w};
#pragma unroll
            for (int i = 0; i < 4; i++)
#pragma unroll
                for (int j = 0; j < 4; j++) dsmac(av[i], bv[j], hi[i][j], lo[i][j]);
        }
        __syncthreads();
    }
#pragma unroll
    for (int i = 0; i < 4; i++) {
        int gm = m0 + ty * 4 + i;
        if (gm >= M) continue;
#pragma unroll
        for (int j = 0; j < 4; j++) {
            int gn = n0 + tx * 4 + j;
            if (gn >= N) continue;
            double v = alpha * ((double)hi[i][j] + (double)lo[i][j]);
            if (bias) v += (double)bias[gn];
            Cm[(long)gm * ldc + gn] = (float)v;
        }
    }
}

// -------- row softmax, warp per row, Ld <= 512, fp64 exp/sum --------
__global__ void softmax_k(float* __restrict__ P, int rows, int Ld) {
    int warp = (blockIdx.x * blockDim.x + threadIdx.x) >> 5;
    int lane = threadIdx.x & 31;
    if (warp >= rows) return;
    float* p = P + (long)warp * Ld;
    float v[16];
    float m = NEG_INF;
#pragma unroll
    for (int q = 0; q < 16; q++) {
        int i = lane + (q << 5);
        v[q] = (i < Ld) ? p[i] : NEG_INF;
        m = fmaxf(m, v[q]);
    }
#pragma unroll
    for (int off = 16; off; off >>= 1) m = fmaxf(m, __shfl_xor_sync(0xffffffffu, m, off));
    double ex[16];
    double s = 0.0;
#pragma unroll
    for (int q = 0; q < 16; q++) {
        int i = lane + (q << 5);
        ex[q] = (i < Ld) ? exp((double)v[q] - (double)m) : 0.0;
        s += ex[q];
    }
#pragma unroll
    for (int off = 16; off; off >>= 1) s += __shfl_xor_sync(0xffffffffu, s, off);
    double inv = 1.0 / s;
#pragma unroll
    for (int q = 0; q < 16; q++) {
        int i = lane + (q << 5);
        if (i < Ld) p[i] = (float)(ex[q] * inv);
    }
}

// -------- GATv2 per graph + mean pool: sort-by-dst, warp-per-dst, no FP atomics --------
__global__ __launch_bounds__(256) void gat_k(
    const float* __restrict__ xfeat, const int* __restrict__ edge_index,
    const float* __restrict__ edge_attr,
    const float* __restrict__ wl, const float* __restrict__ blv,
    const float* __restrict__ wr, const float* __restrict__ brv,
    const float* __restrict__ wev, const float* __restrict__ attv,
    const float* __restrict__ gbias, float* __restrict__ xgraph) {
    int g = blockIdx.x;
    int tid = threadIdx.x;
    int warp = tid >> 5, lane = tid & 31;
    __shared__ float xn[E_];
    __shared__ float xl[2016], xr[2016];
    __shared__ float eav[EPG_];
    __shared__ short srcl[EPG_], dstl[EPG_], sorted_[EPG_];
    __shared__ int deg[63], start_[64], fill[63];
    __shared__ double outrow[2016];
    __shared__ double scbuf[8][64];
    __shared__ float wls[160], wrs[160], wes[32], atts[32];

    const long ebase = (long)g * EPG_;
    for (int i = tid; i < E_; i += 256) xn[i] = xfeat[(long)g * E_ + i];
    if (tid < 160) { wls[tid] = wl[tid]; wrs[tid] = wr[tid]; }
    if (tid < 32)  { wes[tid] = wev[tid]; atts[tid] = attv[tid]; }
    if (tid < 63)  { deg[tid] = 0; fill[tid] = 0; }
    for (int e = tid; e < EPG_; e += 256) {
        srcl[e] = (short)(edge_index[ebase + e] - g * 63);
        dstl[e] = (short)(edge_index[NE_ + ebase + e] - g * 63);
        eav[e]  = edge_attr[ebase + e];
    }
    __syncthreads();
    // projections (fp64 fma, tiny)
    for (int i = tid; i < 2016; i += 256) {
        int nd = i >> 5, k = i & 31;
        const float* xv = &xn[nd * 5];
        double sl = (double)blv[k], sr = (double)brv[k];
#pragma unroll
        for (int f = 0; f < 5; f++) {
            sl = fma((double)wls[k * 5 + f], (double)xv[f], sl);
            sr = fma((double)wrs[k * 5 + f], (double)xv[f], sr);
        }
        xl[i] = (float)sl; xr[i] = (float)sr;
    }
    for (int e = tid; e < EPG_; e += 256) atomicAdd(&deg[dstl[e]], 1);
    __syncthreads();
    if (tid == 0) {
        int a = 0;
        for (int d = 0; d < 63; d++) { start_[d] = a; a += deg[d]; }
        start_[63] = a;
    }
    __syncthreads();
    for (int e = tid; e < EPG_; e += 256) {
        int d = dstl[e];
        int p = start_[d] + atomicAdd(&fill[d], 1);
        sorted_[p] = (short)e;
    }
    __syncthreads();

    for (int d = warp; d < 63; d += 8) {
        int s0 = start_[d];
        int cnt = deg[d];               // real incoming edges; +1 self loop
        // loop-attr mean
        double la = 0.0;
        for (int j = lane; j < cnt; j += 32) la += (double)eav[sorted_[s0 + j]];
#pragma unroll
        for (int off = 16; off; off >>= 1) la += __shfl_xor_sync(0xffffffffu, la, off);
        la /= (double)(cnt > 0 ? cnt : 1);
        // scores (lane-per-edge; j == cnt is the self loop)
        double mx = -1e300;
        for (int j = lane; j <= cnt; j += 32) {
            int src; double ea;
            if (j == cnt) { src = d; ea = la; }
            else { int e = sorted_[s0 + j]; src = srcl[e]; ea = (double)eav[e]; }
            double sco = 0.0;
#pragma unroll
            for (int k = 0; k < 32; k++) {
                double m = (double)xl[src * 32 + k] + (double)xr[d * 32 + k] + (double)wes[k] * ea;
                m = (m > 0.0) ? m : 0.2 * m;
                sco = fma(m, (double)atts[k], sco);
            }
            scbuf[warp][j] = sco;
            mx = fmax(mx, sco);
        }
#pragma unroll
        for (int off = 16; off; off >>= 1) mx = fmax(mx, __shfl_xor_sync(0xffffffffu, mx, off));
        double ssum = 0.0;
        for (int j = lane; j <= cnt; j += 32) {
            double ex = exp(scbuf[warp][j] - mx);
            scbuf[warp][j] = ex;
            ssum += ex;
        }
#pragma unroll
        for (int off = 16; off; off >>= 1) ssum += __shfl_xor_sync(0xffffffffu, ssum, off);
        __syncwarp();
        // feature accumulation: lane = feature k
        double acc = 0.0;
        for (int j = 0; j <= cnt; j++) {
            double ex = scbuf[warp][j];
            int src = (j == cnt) ? d : srcl[sorted_[s0 + j]];
            acc = fma(ex, (double)xl[src * 32 + lane], acc);
        }
        outrow[d * 32 + lane] = acc / ssum;
        __syncwarp();
    }
    __syncthreads();
    if (tid < 32) {
        double s = 0.0;
        for (int d = 0; d < 63; d++) s += outrow[d * 32 + tid];
        xgraph[(long)g * 32 + tid] = (float)(s * (1.0 / 63.0) + (double)gbias[tid]);
    }
}

// -------- GRU scan: one block per batch row, fp64 recurrence, 4-way ILP --------
__global__ __launch_bounds__(192) void gru_k(
    const float* __restrict__ xgates, const float* __restrict__ whh,
    const float* __restrict__ bhh, float* __restrict__ gruout) {
    int b = blockIdx.x;
    int t = threadIdx.x;
    __shared__ double hs[64];
    __shared__ double hg[192];
    double w[64];
#pragma unroll
    for (int j = 0; j < 64; j++) w[j] = (double)whh[t * 64 + j];
    double bh = (double)bhh[t];
    if (t < 64) hs[t] = 0.0;
    __syncthreads();
    for (int l = 0; l < L1_; l++) {
        double s0 = bh, s1 = 0.0, s2 = 0.0, s3 = 0.0;
#pragma unroll
        for (int j = 0; j < 64; j += 4) {
            s0 = fma(w[j],     hs[j],     s0);
            s1 = fma(w[j + 1], hs[j + 1], s1);
            s2 = fma(w[j + 2], hs[j + 2], s2);
            s3 = fma(w[j + 3], hs[j + 3], s3);
        }
        hg[t] = (s0 + s1) + (s2 + s3);
        __syncthreads();
        if (t < 64) {
            const float* xg = xgates + ((long)b * L1_ + l) * 192;
            double r = 1.0 / (1.0 + exp(-((double)xg[t] + hg[t])));
            double z = 1.0 / (1.0 + exp(-((double)xg[64 + t] + hg[64 + t])));
            double n = tanh((double)xg[128 + t] + r * hg[128 + t]);
            double hnew = (1.0 - z) * n + z * hs[t];
            hs[t] = hnew;
            gruout[((long)b * L1_ + l) * 64 + t] = (float)hnew;
        }
        __syncthreads();
    }
}

// -------- classifier, fp64 acc --------
__global__ __launch_bounds__(256) void cls_k(
    const float* __restrict__ gru, const float* __restrict__ w1,
    const float* __restrict__ b1, const float* __restrict__ w2,
    const float* __restrict__ b2, float* __restrict__ sc) {
    __shared__ float s1[2048], s2[96], sb1[32], sb2[3];
    int t = threadIdx.x;
    for (int i = t; i < 2048; i += 256) s1[i] = w1[i];
    if (t < 96) s2[t] = w2[t];
    if (t < 32) sb1[t] = b1[t];
    if (t < 3)  sb2[t] = b2[t];
    __syncthreads();
    int g = blockIdx.x * 256 + t;
    if (g >= G_) return;
    float h[64];
    const float* gr = gru + (long)g * 64;
#pragma unroll
    for (int j = 0; j < 64; j++) h[j] = gr[j];
    double o0 = (double)sb2[0], o1 = (double)sb2[1], o2 = (double)sb2[2];
    for (int u = 0; u < 32; u++) {
        double a = (double)sb1[u];
#pragma unroll
        for (int j = 0; j < 64; j++) a = fma((double)s1[u * 64 + j], (double)h[j], a);
        a = fmax(a, 0.0);
        o0 = fma((double)s2[u], a, o0);
        o1 = fma((double)s2[32 + u], a, o1);
        o2 = fma((double)s2[64 + u], a, o2);
    }
    sc[(long)g * 3 + 0] = (float)o0;
    sc[(long)g * 3 + 1] = (float)o1;
    sc[(long)g * 3 + 2] = (float)o2;
}

// -------- top-5 per (b, class); out: 24 means then 120 idx-as-float --------
__global__ __launch_bounds__(128) void topk_k(const float* __restrict__ scores,
                                              float* __restrict__ out) {
    int bc = blockIdx.x;
    int b = bc / 3, c = bc - 3 * b;
    __shared__ float sv[L1_];
    __shared__ float bval[128];
    __shared__ int bidx[128];
    __shared__ float ssum;
    int t = threadIdx.x;
    for (int i = t; i < L1_; i += 128) sv[i] = scores[((long)b * L1_ + i) * 3 + c];
    if (t == 0) ssum = 0.f;
    __syncthreads();
    for (int k = 0; k < 5; k++) {
        float mv = NEG_INF; int mi = 0x7fffffff;
        for (int i = t; i < L1_; i += 128) {
            float v = sv[i];
            if (v > mv) { mv = v; mi = i; }
        }
        bval[t] = mv; bidx[t] = mi;
        __syncthreads();
        for (int off = 64; off; off >>= 1) {
            if (t < off) {
                if (bval[t + off] > bval[t] ||
                    (bval[t + off] == bval[t] && bidx[t + off] < bidx[t])) {
                    bval[t] = bval[t + off]; bidx[t] = bidx[t + off];
                }
            }
            __syncthreads();
        }
        if (t == 0) {
            out[24 + (b * 5 + k) * 3 + c] = (float)bidx[0];
            ssum += bval[0];
            sv[bidx[0]] = NEG_INF;
        }
        __syncthreads();
    }
    if (t == 0) out[b * 3 + c] = ssum * 0.2f;
}

extern "C" void kernel_launch(void* const* d_in, const int* in_sizes, int n_in,
                              void* d_out, int out_size) {
    const float* x        = (const float*)d_in[0];
    const float* c1w      = (const float*)d_in[1];
    const float* c1b      = (const float*)d_in[2];
    const float* c2w      = (const float*)d_in[3];
    const float* c2b      = (const float*)d_in[4];
    const float* c3w      = (const float*)d_in[5];
    const float* c3b      = (const float*)d_in[6];
    const float* pos_emb  = (const float*)d_in[7];
    const float* ain_w    = (const float*)d_in[8];
    const float* ain_b    = (const float*)d_in[9];
    const float* aout_w   = (const float*)d_in[10];
    const float* aout_b   = (const float*)d_in[11];
    const float* gat_wl   = (const float*)d_in[12];
    const float* gat_bl   = (const float*)d_in[13];
    const float* gat_wr   = (const float*)d_in[14];
    const float* gat_br   = (const float*)d_in[15];
    const float* gat_we   = (const float*)d_in[16];
    const float* gat_att  = (const float*)d_in[17];
    const float* gat_bias = (const float*)d_in[18];
    const float* gru_wih  = (const float*)d_in[19];
    const float* gru_whh  = (const float*)d_in[20];
    const float* gru_bih  = (const float*)d_in[21];
    const float* gru_bhh  = (const float*)d_in[22];
    const float* fc1_w    = (const float*)d_in[23];
    const float* fc1_b    = (const float*)d_in[24];
    const float* fc2_w    = (const float*)d_in[25];
    const float* fc2_b    = (const float*)d_in[26];
    const float* e_attr   = (const float*)d_in[27];
    const int*   e_index  = (const int*)d_in[28];
    float* out = (float*)d_out;

    float* s;
    cudaGetSymbolAddress((void**)&s, g_scratch);
    const double iscale = 0.09759000729485331905;  // 1/sqrt(105)

    // convs (pre-pos chaining)
    conv_k<<<dim3(16, 40), 256>>>(x, c1w, c1b, s + OFF_X1, S_, L1_, 1);
    conv_k<<<dim3(8, 40), 256>>>(s + OFF_X1, c2w, c2b, s + OFF_X2, L1_, L2_, 0);
    conv_k<<<dim3(4, 40), 256>>>(s + OFF_X2, c3w, c3b, s + OFF_X3, L2_, L3_, 0);
    // pos embeddings
    pool_k<<<(L2_ * C_ + 255) / 256, 256>>>(pos_emb, s + OFF_POS2, L1_, L2_);
    pool_k<<<(L3_ * C_ + 255) / 256, 256>>>(s + OFF_POS2, s + OFF_POS3, L2_, L3_);
    addpos_k<<<(int)((SZ_X1 + 255) / 256), 256>>>(s + OFF_X1, pos_emb, L1_);
    addpos_k<<<(int)((SZ_X2 + 255) / 256), 256>>>(s + OFF_X2, s + OFF_POS2, L2_);
    addpos_k<<<(int)((SZ_X3 + 255) / 256), 256>>>(s + OFF_X3, s + OFF_POS3, L3_);

    // ---- MHA1: q = x2 [B,511,315], kv = x3 [B,255,315] ----
    int M1 = B_ * L2_, M3 = B_ * L3_;
    gemm_k<<<dim3(5, (M1 + 63) / 64, 1), 256>>>(s + OFF_X2, 315, 0, 0, ain_w, 315, 0, 0,
        s + OFF_Q1, 315, 0, 0, ain_b, M1, 315, 315, 1.0, 1, 1);
    gemm_k<<<dim3(5, (M3 + 63) / 64, 1), 256>>>(s + OFF_X3, 315, 0, 0, ain_w + 315 * 315, 315, 0, 0,
        s + OFF_KV1, 315, 0, 0, ain_b + 315, M3, 315, 315, 1.0, 1, 1);
    gemm_k<<<dim3(5, (M3 + 63) / 64, 1), 256>>>(s + OFF_X3, 315, 0, 0, ain_w + 630 * 315, 315, 0, 0,
        s + OFF_KV1 + (long)M3 * 315, 315, 0, 0, ain_b + 630, M3, 315, 315, 1.0, 1, 1);
    gemm_k<<<dim3(4, 8, 24), 256>>>(
        s + OFF_Q1, 315, (long)L2_ * 315, 105,
        s + OFF_KV1, 315, (long)L3_ * 315, 105,
        s + OFF_P1, 255, (long)3 * L2_ * L3_, (long)L2_ * L3_,
        nullptr, L2_, L3_, 105, iscale, 1, 3);
    softmax_k<<<(B_ * 3 * L2_ + 7) / 8, 256>>>(s + OFF_P1, B_ * 3 * L2_, L3_);
    gemm_k<<<dim3(2, 8, 24), 256>>>(
        s + OFF_P1, 255, (long)3 * L2_ * L3_, (long)L2_ * L3_,
        s + OFF_KV1 + (long)M3 * 315, 315, (long)L3_ * 315, 105,
        s + OFF_O1, 315, (long)L2_ * 315, 105,
        nullptr, L2_, 105, L3_, 1.0, 0, 3);
    gemm_k<<<dim3(5, (M1 + 63) / 64, 1), 256>>>(s + OFF_O1, 315, 0, 0, aout_w, 315, 0, 0,
        s + OFF_X2A, 315, 0, 0, aout_b, M1, 315, 315, 1.0, 1, 1);

    // ---- MHA2: q = x1 [B,1023,315], kv = x2a [B,511,315] ----
    int M0 = B_ * L1_;
    gemm_k<<<dim3(5, (M0 + 63) / 64, 1), 256>>>(s + OFF_X1, 315, 0, 0, ain_w, 315, 0, 0,
        s + OFF_Q2, 315, 0, 0, ain_b, M0, 315, 315, 1.0, 1, 1);
    gemm_k<<<dim3(5, (M1 + 63) / 64, 1), 256>>>(s + OFF_X2A, 315, 0, 0, ain_w + 315 * 315, 315, 0, 0,
        s + OFF_KV2, 315, 0, 0, ain_b + 315, M1, 315, 315, 1.0, 1, 1);
    gemm_k<<<dim3(5, (M1 + 63) / 64, 1), 256>>>(s + OFF_X2A, 315, 0, 0, ain_w + 630 * 315, 315, 0, 0,
        s + OFF_KV2 + (long)M1 * 315, 315, 0, 0, ain_b + 630, M1, 315, 315, 1.0, 1, 1);
    gemm_k<<<dim3(8, 16, 24), 256>>>(
        s + OFF_Q2, 315, (long)L1_ * 315, 105,
        s + OFF_KV2, 315, (long)L2_ * 315, 105,
        s + OFF_P2, 511, (long)3 * L1_ * L2_, (long)L1_ * L2_,
        nullptr, L1_, L2_, 105, iscale, 1, 3);
    softmax_k<<<(B_ * 3 * L1_ + 7) / 8, 256>>>(s + OFF_P2, B_ * 3 * L1_, L2_);
    gemm_k<<<dim3(2, 16, 24), 256>>>(
        s + OFF_P2, 511, (long)3 * L1_ * L2_, (long)L1_ * L2_,
        s + OFF_KV2 + (long)M1 * 315, 315, (long)L2_ * 315, 105,
        s + OFF_O2, 315, (long)L1_ * 315, 105,
        nullptr, L1_, 105, L2_, 1.0, 0, 3);
    gemm_k<<<dim3(5, (M0 + 63) / 64, 1), 256>>>(s + OFF_O2, 315, 0, 0, aout_w, 315, 0, 0,
        s + OFF_X1A, 315, 0, 0, aout_b, M0, 315, 315, 1.0, 1, 1);

    // ---- GAT per graph ----
    gat_k<<<G_, 256>>>(s + OFF_X1A, e_index, e_attr,
                       gat_wl, gat_bl, gat_wr, gat_br, gat_we, gat_att, gat_bias,
                       s + OFF_XGRAPH);

    // ---- GRU input gates + scan ----
    gemm_k<<<dim3(3, (G_ + 63) / 64, 1), 256>>>(s + OFF_XGRAPH, 32, 0, 0, gru_wih, 32, 0, 0,
        s + OFF_XGATES, 192, 0, 0, gru_bih, G_, 192, 32, 1.0, 1, 1);
    gru_k<<<B_, 192>>>(s + OFF_XGATES, gru_whh, gru_bhh, s + OFF_GRUOUT);

    // ---- classifier + top-k ----
    cls_k<<<(G_ + 255) / 256, 256>>>(s + OFF_GRUOUT, fc1_w, fc1_b, fc2_w, fc2_b,
                                     s + OFF_SCORES);
    topk_k<<<24, 128>>>(s + OFF_SCORES, out);
}

// round 6
// speedup vs baseline: 1.3225x; 1.0162x over previous
#include <cuda_runtime.h>
#include <math.h>

#define B_    8
#define C_    63
#define S_    2048
#define F_    5
#define E_    315
#define L1_   1023
#define L2_   511
#define L3_   255
#define O_    32
#define H_    64
#define EPG_  504
#define G_    (B_*L1_)
#define NE_   ((long)G_*EPG_)
#define NEG_INF (-3.402823466e38f)

constexpr long SZ_X1     = (long)B_*L1_*E_;
constexpr long SZ_X2     = (long)B_*L2_*E_;
constexpr long SZ_X3     = (long)B_*L3_*E_;
constexpr long SZ_POS2   = (long)L2_*C_;
constexpr long SZ_POS3   = (long)L3_*C_;
constexpr long SZ_Q1     = (long)B_*L2_*E_;
constexpr long SZ_KV1    = (long)B_*L3_*2*E_;
constexpr long SZ_P1     = (long)B_*3*L2_*L3_;
constexpr long SZ_O1     = SZ_Q1;
constexpr long SZ_X2A    = SZ_Q1;
constexpr long SZ_Q2     = (long)B_*L1_*E_;
constexpr long SZ_KV2    = (long)B_*L2_*2*E_;
constexpr long SZ_P2     = (long)B_*3*L1_*L2_;
constexpr long SZ_O2     = SZ_Q2;
constexpr long SZ_X1A    = SZ_Q2;
constexpr long SZ_XGRAPH = (long)G_*O_;
constexpr long SZ_XGATES = (long)G_*3*H_;
constexpr long SZ_GRUOUT = (long)G_*H_;
constexpr long SZ_SCORES = (long)G_*3;

constexpr long OFF_X1     = 0;
constexpr long OFF_X2     = OFF_X1     + SZ_X1;
constexpr long OFF_X3     = OFF_X2     + SZ_X2;
constexpr long OFF_POS2   = OFF_X3     + SZ_X3;
constexpr long OFF_POS3   = OFF_POS2   + SZ_POS2;
constexpr long OFF_Q1     = OFF_POS3   + SZ_POS3;
constexpr long OFF_KV1    = OFF_Q1     + SZ_Q1;
constexpr long OFF_P1     = OFF_KV1    + SZ_KV1;
constexpr long OFF_O1     = OFF_P1     + SZ_P1;
constexpr long OFF_X2A    = OFF_O1     + SZ_O1;
constexpr long OFF_Q2     = OFF_X2A    + SZ_X2A;
constexpr long OFF_KV2    = OFF_Q2     + SZ_Q2;
constexpr long OFF_P2     = OFF_KV2    + SZ_KV2;
constexpr long OFF_O2     = OFF_P2     + SZ_P2;
constexpr long OFF_X1A    = OFF_O2     + SZ_O2;
constexpr long OFF_XGRAPH = OFF_X1A    + SZ_X1A;
constexpr long OFF_XGATES = OFF_XGRAPH + SZ_XGRAPH;
constexpr long OFF_GRUOUT = OFF_XGATES + SZ_XGATES;
constexpr long OFF_SCORES = OFF_GRUOUT + SZ_GRUOUT;
constexpr long SCRATCH_TOTAL = OFF_SCORES + SZ_SCORES;

__device__ float g_scratch[SCRATCH_TOTAL];

// double-single compensated MAC: (hi,lo) += a*b, exact product + Knuth TwoSum.
__device__ __forceinline__ void dsmac(float a, float b, float& hi, float& lo) {
    float p  = __fmul_rn(a, b);
    float e  = __fmaf_rn(a, b, -p);
    float s  = __fadd_rn(hi, p);
    float bb = __fsub_rn(s, hi);
    float err = __fadd_rn(__fsub_rn(hi, __fsub_rn(s, bb)), __fsub_rn(p, bb));
    hi = s;
    lo = __fadd_rn(lo, __fadd_rn(err, e));
}

// -------- adaptive avg pool over first dim of [L, 63] (fp64 acc) --------
__global__ void pool_k(const float* __restrict__ in, float* __restrict__ out,
                       int Lin, int Lout) {
    int idx = blockIdx.x * blockDim.x + threadIdx.x;
    if (idx >= Lout * C_) return;
    int i = idx / C_, c = idx - C_ * i;
    int s = (i * Lin) / Lout;
    int e = ((i + 1) * Lin + Lout - 1) / Lout;
    double acc = 0.0;
    for (int l = s; l < e; l++) acc += (double)in[l * C_ + c];
    out[idx] = (float)(acc / (double)(e - s));
}

// -------- conv (1x3, stride2, 63->63 channel mix), df64 acc, double-buffered --------
__global__ __launch_bounds__(256) void conv_k(
    const float* __restrict__ in, const float* __restrict__ W,
    const float* __restrict__ bias, float* __restrict__ out,
    int Lin, int Lout, int inOrig) {
    int l0 = blockIdx.x * 64;
    int bf = blockIdx.y;
    int b = bf / F_, f = bf - b * F_;
    __shared__ __align__(16) float As[2][16][68];
    __shared__ __align__(16) float Bs[2][16][68];
    int tid = threadIdx.x;
    int tx = tid & 15, ty = tid >> 4;
    float hi[4][4], lo[4][4];
#pragma unroll
    for (int i = 0; i < 4; i++)
#pragma unroll
        for (int j = 0; j < 4; j++) { hi[i][j] = 0.f; lo[i][j] = 0.f; }

    const int akk = tid & 15, amb = tid >> 4;     // A: kk fixed, m = amb + 16q
    const int bn = tid & 63, bkb = tid >> 6;      // B: n fixed, kk = bkb + 4q
    float ra[4], rb[4];

    auto loadA = [&](int k0) {
        int kidx = k0 + akk;
#pragma unroll
        for (int q = 0; q < 4; q++) {
            int co = amb + q * 16;
            ra[q] = (co < 63 && kidx < 189) ? W[co * 189 + kidx] : 0.f;
        }
    };
    auto loadB = [&](int k0) {
        int gl = l0 + bn;
#pragma unroll
        for (int q = 0; q < 4; q++) {
            int kidx = k0 + bkb + q * 4;
            float v = 0.f;
            if (kidx < 189 && gl < Lout) {
                int ci = kidx / 3, kx = kidx - ci * 3;
                int si = 2 * gl + kx;
                if (inOrig)
                    v = in[((long)(b * 63 + ci) * Lin + si) * 5 + f];
                else
                    v = in[((long)b * Lin + si) * 315 + f * 63 + ci];
            }
            rb[q] = v;
        }
    };

    loadA(0); loadB(0);
    int buf = 0;
    for (int k0 = 0; k0 < 192; k0 += 16) {
#pragma unroll
        for (int q = 0; q < 4; q++) As[buf][akk][amb + q * 16] = ra[q];
#pragma unroll
        for (int q = 0; q < 4; q++) Bs[buf][bkb + q * 4][bn] = rb[q];
        __syncthreads();
        if (k0 + 16 < 192) { loadA(k0 + 16); loadB(k0 + 16); }
#pragma unroll
        for (int kk = 0; kk < 16; kk++) {
            float4 a4 = *(const float4*)&As[buf][kk][ty * 4];
            float4 b4 = *(const float4*)&Bs[buf][kk][tx * 4];
            float av[4] = {a4.x, a4.y, a4.z, a4.w};
            float bv[4] = {b4.x, b4.y, b4.z, b4.w};
#pragma unroll
            for (int i = 0; i < 4; i++)
#pragma unroll
                for (int j = 0; j < 4; j++) dsmac(av[i], bv[j], hi[i][j], lo[i][j]);
        }
        buf ^= 1;
    }
#pragma unroll
    for (int i = 0; i < 4; i++) {
        int co = ty * 4 + i;
        if (co >= 63) continue;
#pragma unroll
        for (int j = 0; j < 4; j++) {
            int l = l0 + tx * 4 + j;
            if (l >= Lout) continue;
            double v = (double)hi[i][j] + (double)lo[i][j] + (double)bias[co];
            out[((long)b * Lout + l) * 315 + f * 63 + co] = (float)v;
        }
    }
}

// add pos (layout [L,63]) to flat tensor [B,L,315]
__global__ void addpos_k(float* __restrict__ xf, const float* __restrict__ pos, int L) {
    long idx = (long)blockIdx.x * 256 + threadIdx.x;
    long tot = (long)B_ * L * 315;
    if (idx >= tot) return;
    int rem = (int)(idx % 315);
    long bl = idx / 315;
    int l = (int)(bl % L);
    xf[idx] += pos[l * 63 + (rem % 63)];
}

// -------- generic GEMM, fp32 in/out, df64 acc, double-buffered pipeline --------
__global__ __launch_bounds__(256) void gemm_k(
    const float* __restrict__ A, int lda, long sAo, long sAi,
    const float* __restrict__ Bm, int ldb, long sBo, long sBi,
    float* __restrict__ Cm, int ldc, long sCo, long sCi,
    const float* __restrict__ bias,
    int M, int N, int K, double alpha, int transB, int nInner) {
    int z = blockIdx.z;
    int zo = z / nInner, zi = z - zo * nInner;
    A += zo * sAo + zi * sAi;
    Bm += zo * sBo + zi * sBi;
    Cm += zo * sCo + zi * sCi;
    __shared__ __align__(16) float As[2][16][68];
    __shared__ __align__(16) float Bs[2][16][68];
    int m0 = blockIdx.y * 64, n0 = blockIdx.x * 64;
    int tid = threadIdx.x;
    int tx = tid & 15, ty = tid >> 4;
    float hi[4][4], lo[4][4];
#pragma unroll
    for (int i = 0; i < 4; i++)
#pragma unroll
        for (int j = 0; j < 4; j++) { hi[i][j] = 0.f; lo[i][j] = 0.f; }

    const int akk = tid & 15, amb = tid >> 4;   // A & transB-B: kk fixed, row = amb+16q
    const int bn = tid & 63, bkb = tid >> 6;    // notrans-B: n fixed, kk = bkb+4q
    float ra[4], rb[4];

    auto loadA = [&](int k0) {
        int gk = k0 + akk;
        bool kok = gk < K;
#pragma unroll
        for (int q = 0; q < 4; q++) {
            int gm = m0 + amb + q * 16;
            ra[q] = (gm < M && kok) ? A[(long)gm * lda + gk] : 0.f;
        }
    };
    auto loadB = [&](int k0) {
        if (transB) {
            int gk = k0 + akk;
            bool kok = gk < K;
#pragma unroll
            for (int q = 0; q < 4; q++) {
                int gn = n0 + amb + q * 16;
                rb[q] = (gn < N && kok) ? Bm[(long)gn * ldb + gk] : 0.f;
            }
        } else {
            int gn = n0 + bn;
            bool nok = gn < N;
#pragma unroll
            for (int q = 0; q < 4; q++) {
                int gk = k0 + bkb + q * 4;
                rb[q] = (nok && gk < K) ? Bm[(long)gk * ldb + gn] : 0.f;
            }
        }
    };

    loadA(0); loadB(0);
    int buf = 0;
    for (int k0 = 0; k0 < K; k0 += 16) {
#pragma unroll
        for (int q = 0; q < 4; q++) As[buf][akk][amb + q * 16] = ra[q];
        if (transB) {
#pragma unroll
            for (int q = 0; q < 4; q++) Bs[buf][akk][amb + q * 16] = rb[q];
        } else {
#pragma unroll
            for (int q = 0; q < 4; q++) Bs[buf][bkb + q * 4][bn] = rb[q];
        }
        __syncthreads();
        if (k0 + 16 < K) { loadA(k0 + 16); loadB(k0 + 16); }
#pragma unroll
        for (int kk = 0; kk < 16; kk++) {
            float4 a4 = *(const float4*)&As[buf][kk][ty * 4];
            float4 b4 = *(const float4*)&Bs[buf][kk][tx * 4];
            float av[4] = {a4.x, a4.y, a4.z, a4.w};
            float bv[4] = {b4.x, b4.y, b4.z, b4.w};
#pragma unroll
            for (int i = 0; i < 4; i++)
#pragma unroll
                for (int j = 0; j < 4; j++) dsmac(av[i], bv[j], hi[i][j], lo[i][j]);
        }
        buf ^= 1;
    }
#pragma unroll
    for (int i = 0; i < 4; i++) {
        int gm = m0 + ty * 4 + i;
        if (gm >= M) continue;
#pragma unroll
        for (int j = 0; j < 4; j++) {
            int gn = n0 + tx * 4 + j;
            if (gn >= N) continue;
            double v = alpha * ((double)hi[i][j] + (double)lo[i][j]);
            if (bias) v += (double)bias[gn];
            Cm[(long)gm * ldc + gn] = (float)v;
        }
    }
}

// -------- row softmax, warp per row, Ld <= 512, fp64 exp/sum --------
__global__ void softmax_k(float* __restrict__ P, int rows, int Ld) {
    int warp = (blockIdx.x * blockDim.x + threadIdx.x) >> 5;
    int lane = threadIdx.x & 31;
    if (warp >= rows) return;
    float* p = P + (long)warp * Ld;
    float v[16];
    float m = NEG_INF;
#pragma unroll
    for (int q = 0; q < 16; q++) {
        int i = lane + (q << 5);
        v[q] = (i < Ld) ? p[i] : NEG_INF;
        m = fmaxf(m, v[q]);
    }
#pragma unroll
    for (int off = 16; off; off >>= 1) m = fmaxf(m, __shfl_xor_sync(0xffffffffu, m, off));
    double ex[16];
    double s = 0.0;
#pragma unroll
    for (int q = 0; q < 16; q++) {
        int i = lane + (q << 5);
        ex[q] = (i < Ld) ? exp((double)v[q] - (double)m) : 0.0;
        s += ex[q];
    }
#pragma unroll
    for (int off = 16; off; off >>= 1) s += __shfl_xor_sync(0xffffffffu, s, off);
    double inv = 1.0 / s;
#pragma unroll
    for (int q = 0; q < 16; q++) {
        int i = lane + (q << 5);
        if (i < Ld) p[i] = (float)(ex[q] * inv);
    }
}

// -------- GATv2 per graph + mean pool: sort-by-dst, warp-per-dst --------
__global__ __launch_bounds__(256) void gat_k(
    const float* __restrict__ xfeat, const int* __restrict__ edge_index,
    const float* __restrict__ edge_attr,
    const float* __restrict__ wl, const float* __restrict__ blv,
    const float* __restrict__ wr, const float* __restrict__ brv,
    const float* __restrict__ wev, const float* __restrict__ attv,
    const float* __restrict__ gbias, float* __restrict__ xgraph) {
    int g = blockIdx.x;
    int tid = threadIdx.x;
    int warp = tid >> 5, lane = tid & 31;
    __shared__ float xn[E_];
    __shared__ float xl[2016], xr[2016];
    __shared__ float eav[EPG_];
    __shared__ short srcl[EPG_], dstl[EPG_], sorted_[EPG_];
    __shared__ int deg[63], start_[64], fill[63];
    __shared__ double outrow[2016];
    __shared__ double scbuf[8][64];
    __shared__ float wls[160], wrs[160], wes[32], atts[32];

    const long ebase = (long)g * EPG_;
    for (int i = tid; i < E_; i += 256) xn[i] = xfeat[(long)g * E_ + i];
    if (tid < 160) { wls[tid] = wl[tid]; wrs[tid] = wr[tid]; }
    if (tid < 32)  { wes[tid] = wev[tid]; atts[tid] = attv[tid]; }
    if (tid < 63)  { deg[tid] = 0; fill[tid] = 0; }
    for (int e = tid; e < EPG_; e += 256) {
        srcl[e] = (short)(edge_index[ebase + e] - g * 63);
        dstl[e] = (short)(edge_index[NE_ + ebase + e] - g * 63);
        eav[e]  = edge_attr[ebase + e];
    }
    __syncthreads();
    for (int i = tid; i < 2016; i += 256) {
        int nd = i >> 5, k = i & 31;
        const float* xv = &xn[nd * 5];
        double sl = (double)blv[k], sr = (double)brv[k];
#pragma unroll
        for (int f = 0; f < 5; f++) {
            sl = fma((double)wls[k * 5 + f], (double)xv[f], sl);
            sr = fma((double)wrs[k * 5 + f], (double)xv[f], sr);
        }
        xl[i] = (float)sl; xr[i] = (float)sr;
    }
    for (int e = tid; e < EPG_; e += 256) atomicAdd(&deg[dstl[e]], 1);
    __syncthreads();
    if (tid == 0) {
        int a = 0;
        for (int d = 0; d < 63; d++) { start_[d] = a; a += deg[d]; }
        start_[63] = a;
    }
    __syncthreads();
    for (int e = tid; e < EPG_; e += 256) {
        int d = dstl[e];
        int p = start_[d] + atomicAdd(&fill[d], 1);
        sorted_[p] = (short)e;
    }
    __syncthreads();

    for (int d = warp; d < 63; d += 8) {
        int s0 = start_[d];
        int cnt = deg[d];
        double la = 0.0;
        for (int j = lane; j < cnt; j += 32) la += (double)eav[sorted_[s0 + j]];
#pragma unroll
        for (int off = 16; off; off >>= 1) la += __shfl_xor_sync(0xffffffffu, la, off);
        la /= (double)(cnt > 0 ? cnt : 1);
        double mx = -1e300;
        for (int j = lane; j <= cnt; j += 32) {
            int src; double ea;
            if (j == cnt) { src = d; ea = la; }
            else { int e = sorted_[s0 + j]; src = srcl[e]; ea = (double)eav[e]; }
            double sco = 0.0;
#pragma unroll
            for (int k = 0; k < 32; k++) {
                double m = (double)xl[src * 32 + k] + (double)xr[d * 32 + k] + (double)wes[k] * ea;
                m = (m > 0.0) ? m : 0.2 * m;
                sco = fma(m, (double)atts[k], sco);
            }
            scbuf[warp][j] = sco;
            mx = fmax(mx, sco);
        }
#pragma unroll
        for (int off = 16; off; off >>= 1) mx = fmax(mx, __shfl_xor_sync(0xffffffffu, mx, off));
        double ssum = 0.0;
        for (int j = lane; j <= cnt; j += 32) {
            double ex = exp(scbuf[warp][j] - mx);
            scbuf[warp][j] = ex;
            ssum += ex;
        }
#pragma unroll
        for (int off = 16; off; off >>= 1) ssum += __shfl_xor_sync(0xffffffffu, ssum, off);
        __syncwarp();
        double acc = 0.0;
        for (int j = 0; j <= cnt; j++) {
            double ex = scbuf[warp][j];
            int src = (j == cnt) ? d : srcl[sorted_[s0 + j]];
            acc = fma(ex, (double)xl[src * 32 + lane], acc);
        }
        outrow[d * 32 + lane] = acc / ssum;
        __syncwarp();
    }
    __syncthreads();
    if (tid < 32) {
        double s = 0.0;
        for (int d = 0; d < 63; d++) s += outrow[d * 32 + tid];
        xgraph[(long)g * 32 + tid] = (float)(s * (1.0 / 63.0) + (double)gbias[tid]);
    }
}

// -------- GRU scan: one block per batch row, fp64 recurrence, 4-way ILP --------
__global__ __launch_bounds__(192) void gru_k(
    const float* __restrict__ xgates, const float* __restrict__ whh,
    const float* __restrict__ bhh, float* __restrict__ gruout) {
    int b = blockIdx.x;
    int t = threadIdx.x;
    __shared__ double hs[64];
    __shared__ double hg[192];
    double w[64];
#pragma unroll
    for (int j = 0; j < 64; j++) w[j] = (double)whh[t * 64 + j];
    double bh = (double)bhh[t];
    if (t < 64) hs[t] = 0.0;
    __syncthreads();
    for (int l = 0; l < L1_; l++) {
        double s0 = bh, s1 = 0.0, s2 = 0.0, s3 = 0.0;
#pragma unroll
        for (int j = 0; j < 64; j += 4) {
            s0 = fma(w[j],     hs[j],     s0);
            s1 = fma(w[j + 1], hs[j + 1], s1);
            s2 = fma(w[j + 2], hs[j + 2], s2);
            s3 = fma(w[j + 3], hs[j + 3], s3);
        }
        hg[t] = (s0 + s1) + (s2 + s3);
        __syncthreads();
        if (t < 64) {
            const float* xg = xgates + ((long)b * L1_ + l) * 192;
            double r = 1.0 / (1.0 + exp(-((double)xg[t] + hg[t])));
            double z = 1.0 / (1.0 + exp(-((double)xg[64 + t] + hg[64 + t])));
            double n = tanh((double)xg[128 + t] + r * hg[128 + t]);
            double hnew = (1.0 - z) * n + z * hs[t];
            hs[t] = hnew;
            gruout[((long)b * L1_ + l) * 64 + t] = (float)hnew;
        }
        __syncthreads();
    }
}

// -------- classifier, fp64 acc --------
__global__ __launch_bounds__(256) void cls_k(
    const float* __restrict__ gru, const float* __restrict__ w1,
    const float* __restrict__ b1, const float* __restrict__ w2,
    const float* __restrict__ b2, float* __restrict__ sc) {
    __shared__ float s1[2048], s2[96], sb1[32], sb2[3];
    int t = threadIdx.x;
    for (int i = t; i < 2048; i += 256) s1[i] = w1[i];
    if (t < 96) s2[t] = w2[t];
    if (t < 32) sb1[t] = b1[t];
    if (t < 3)  sb2[t] = b2[t];
    __syncthreads();
    int g = blockIdx.x * 256 + t;
    if (g >= G_) return;
    float h[64];
    const float* gr = gru + (long)g * 64;
#pragma unroll
    for (int j = 0; j < 64; j++) h[j] = gr[j];
    double o0 = (double)sb2[0], o1 = (double)sb2[1], o2 = (double)sb2[2];
    for (int u = 0; u < 32; u++) {
        double a = (double)sb1[u];
#pragma unroll
        for (int j = 0; j < 64; j++) a = fma((double)s1[u * 64 + j], (double)h[j], a);
        a = fmax(a, 0.0);
        o0 = fma((double)s2[u], a, o0);
        o1 = fma((double)s2[32 + u], a, o1);
        o2 = fma((double)s2[64 + u], a, o2);
    }
    sc[(long)g * 3 + 0] = (float)o0;
    sc[(long)g * 3 + 1] = (float)o1;
    sc[(long)g * 3 + 2] = (float)o2;
}

// -------- top-5 per (b, class); out: 24 means then 120 idx-as-float --------
__global__ __launch_bounds__(128) void topk_k(const float* __restrict__ scores,
                                              float* __restrict__ out) {
    int bc = blockIdx.x;
    int b = bc / 3, c = bc - 3 * b;
    __shared__ float sv[L1_];
    __shared__ float bval[128];
    __shared__ int bidx[128];
    __shared__ float ssum;
    int t = threadIdx.x;
    for (int i = t; i < L1_; i += 128) sv[i] = scores[((long)b * L1_ + i) * 3 + c];
    if (t == 0) ssum = 0.f;
    __syncthreads();
    for (int k = 0; k < 5; k++) {
        float mv = NEG_INF; int mi = 0x7fffffff;
        for (int i = t; i < L1_; i += 128) {
            float v = sv[i];
            if (v > mv) { mv = v; mi = i; }
        }
        bval[t] = mv; bidx[t] = mi;
        __syncthreads();
        for (int off = 64; off; off >>= 1) {
            if (t < off) {
                if (bval[t + off] > bval[t] ||
                    (bval[t + off] == bval[t] && bidx[t + off] < bidx[t])) {
                    bval[t] = bval[t + off]; bidx[t] = bidx[t + off];
                }
            }
            __syncthreads();
        }
        if (t == 0) {
            out[24 + (b * 5 + k) * 3 + c] = (float)bidx[0];
            ssum += bval[0];
            sv[bidx[0]] = NEG_INF;
        }
        __syncthreads();
    }
    if (t == 0) out[b * 3 + c] = ssum * 0.2f;
}

extern "C" void kernel_launch(void* const* d_in, const int* in_sizes, int n_in,
                              void* d_out, int out_size) {
    const float* x        = (const float*)d_in[0];
    const float* c1w      = (const float*)d_in[1];
    const float* c1b      = (const float*)d_in[2];
    const float* c2w      = (const float*)d_in[3];
    const float* c2b      = (const float*)d_in[4];
    const float* c3w      = (const float*)d_in[5];
    const float* c3b      = (const float*)d_in[6];
    const float* pos_emb  = (const float*)d_in[7];
    const float* ain_w    = (const float*)d_in[8];
    const float* ain_b    = (const float*)d_in[9];
    const float* aout_w   = (const float*)d_in[10];
    const float* aout_b   = (const float*)d_in[11];
    const float* gat_wl   = (const float*)d_in[12];
    const float* gat_bl   = (const float*)d_in[13];
    const float* gat_wr   = (const float*)d_in[14];
    const float* gat_br   = (const float*)d_in[15];
    const float* gat_we   = (const float*)d_in[16];
    const float* gat_att  = (const float*)d_in[17];
    const float* gat_bias = (const float*)d_in[18];
    const float* gru_wih  = (const float*)d_in[19];
    const float* gru_whh  = (const float*)d_in[20];
    const float* gru_bih  = (const float*)d_in[21];
    const float* gru_bhh  = (const float*)d_in[22];
    const float* fc1_w    = (const float*)d_in[23];
    const float* fc1_b    = (const float*)d_in[24];
    const float* fc2_w    = (const float*)d_in[25];
    const float* fc2_b    = (const float*)d_in[26];
    const float* e_attr   = (const float*)d_in[27];
    const int*   e_index  = (const int*)d_in[28];
    float* out = (float*)d_out;

    float* s;
    cudaGetSymbolAddress((void**)&s, g_scratch);
    const double iscale = 0.09759000729485331905;  // 1/sqrt(105)

    conv_k<<<dim3(16, 40), 256>>>(x, c1w, c1b, s + OFF_X1, S_, L1_, 1);
    conv_k<<<dim3(8, 40), 256>>>(s + OFF_X1, c2w, c2b, s + OFF_X2, L1_, L2_, 0);
    conv_k<<<dim3(4, 40), 256>>>(s + OFF_X2, c3w, c3b, s + OFF_X3, L2_, L3_, 0);
    pool_k<<<(L2_ * C_ + 255) / 256, 256>>>(pos_emb, s + OFF_POS2, L1_, L2_);
    pool_k<<<(L3_ * C_ + 255) / 256, 256>>>(s + OFF_POS2, s + OFF_POS3, L2_, L3_);
    addpos_k<<<(int)((SZ_X1 + 255) / 256), 256>>>(s + OFF_X1, pos_emb, L1_);
    addpos_k<<<(int)((SZ_X2 + 255) / 256), 256>>>(s + OFF_X2, s + OFF_POS2, L2_);
    addpos_k<<<(int)((SZ_X3 + 255) / 256), 256>>>(s + OFF_X3, s + OFF_POS3, L3_);

    // ---- MHA1 ----
    int M1 = B_ * L2_, M3 = B_ * L3_;
    gemm_k<<<dim3(5, (M1 + 63) / 64, 1), 256>>>(s + OFF_X2, 315, 0, 0, ain_w, 315, 0, 0,
        s + OFF_Q1, 315, 0, 0, ain_b, M1, 315, 315, 1.0, 1, 1);
    gemm_k<<<dim3(5, (M3 + 63) / 64, 1), 256>>>(s + OFF_X3, 315, 0, 0, ain_w + 315 * 315, 315, 0, 0,
        s + OFF_KV1, 315, 0, 0, ain_b + 315, M3, 315, 315, 1.0, 1, 1);
    gemm_k<<<dim3(5, (M3 + 63) / 64, 1), 256>>>(s + OFF_X3, 315, 0, 0, ain_w + 630 * 315, 315, 0, 0,
        s + OFF_KV1 + (long)M3 * 315, 315, 0, 0, ain_b + 630, M3, 315, 315, 1.0, 1, 1);
    gemm_k<<<dim3(4, 8, 24), 256>>>(
        s + OFF_Q1, 315, (long)L2_ * 315, 105,
        s + OFF_KV1, 315, (long)L3_ * 315, 105,
        s + OFF_P1, 255, (long)3 * L2_ * L3_, (long)L2_ * L3_,
        nullptr, L2_, L3_, 105, iscale, 1, 3);
    softmax_k<<<(B_ * 3 * L2_ + 7) / 8, 256>>>(s + OFF_P1, B_ * 3 * L2_, L3_);
    gemm_k<<<dim3(2, 8, 24), 256>>>(
        s + OFF_P1, 255, (long)3 * L2_ * L3_, (long)L2_ * L3_,
        s + OFF_KV1 + (long)M3 * 315, 315, (long)L3_ * 315, 105,
        s + OFF_O1, 315, (long)L2_ * 315, 105,
        nullptr, L2_, 105, L3_, 1.0, 0, 3);
    gemm_k<<<dim3(5, (M1 + 63) / 64, 1), 256>>>(s + OFF_O1, 315, 0, 0, aout_w, 315, 0, 0,
        s + OFF_X2A, 315, 0, 0, aout_b, M1, 315, 315, 1.0, 1, 1);

    // ---- MHA2 ----
    int M0 = B_ * L1_;
    gemm_k<<<dim3(5, (M0 + 63) / 64, 1), 256>>>(s + OFF_X1, 315, 0, 0, ain_w, 315, 0, 0,
        s + OFF_Q2, 315, 0, 0, ain_b, M0, 315, 315, 1.0, 1, 1);
    gemm_k<<<dim3(5, (M1 + 63) / 64, 1), 256>>>(s + OFF_X2A, 315, 0, 0, ain_w + 315 * 315, 315, 0, 0,
        s + OFF_KV2, 315, 0, 0, ain_b + 315, M1, 315, 315, 1.0, 1, 1);
    gemm_k<<<dim3(5, (M1 + 63) / 64, 1), 256>>>(s + OFF_X2A, 315, 0, 0, ain_w + 630 * 315, 315, 0, 0,
        s + OFF_KV2 + (long)M1 * 315, 315, 0, 0, ain_b + 630, M1, 315, 315, 1.0, 1, 1);
    gemm_k<<<dim3(8, 16, 24), 256>>>(
        s + OFF_Q2, 315, (long)L1_ * 315, 105,
        s + OFF_KV2, 315, (long)L2_ * 315, 105,
        s + OFF_P2, 511, (long)3 * L1_ * L2_, (long)L1_ * L2_,
        nullptr, L1_, L2_, 105, iscale, 1, 3);
    softmax_k<<<(B_ * 3 * L1_ + 7) / 8, 256>>>(s + OFF_P2, B_ * 3 * L1_, L2_);
    gemm_k<<<dim3(2, 16, 24), 256>>>(
        s + OFF_P2, 511, (long)3 * L1_ * L2_, (long)L1_ * L2_,
        s + OFF_KV2 + (long)M1 * 315, 315, (long)L2_ * 315, 105,
        s + OFF_O2, 315, (long)L1_ * 315, 105,
        nullptr, L1_, 105, L2_, 1.0, 0, 3);
    gemm_k<<<dim3(5, (M0 + 63) / 64, 1), 256>>>(s + OFF_O2, 315, 0, 0, aout_w, 315, 0, 0,
        s + OFF_X1A, 315, 0, 0, aout_b, M0, 315, 315, 1.0, 1, 1);

    // ---- GAT / GRU / classifier / topk ----
    gat_k<<<G_, 256>>>(s + OFF_X1A, e_index, e_attr,
                       gat_wl, gat_bl, gat_wr, gat_br, gat_we, gat_att, gat_bias,
                       s + OFF_XGRAPH);
    gemm_k<<<dim3(3, (G_ + 63) / 64, 1), 256>>>(s + OFF_XGRAPH, 32, 0, 0, gru_wih, 32, 0, 0,
        s + OFF_XGATES, 192, 0, 0, gru_bih, G_, 192, 32, 1.0, 1, 1);
    gru_k<<<B_, 192>>>(s + OFF_XGATES, gru_whh, gru_bhh, s + OFF_GRUOUT);
    cls_k<<<(G_ + 255) / 256, 256>>>(s + OFF_GRUOUT, fc1_w, fc1_b, fc2_w, fc2_b,
                                     s + OFF_SCORES);
    topk_k<<<24, 128>>>(s + OFF_SCORES, out);
}